// round 13
// baseline (speedup 1.0000x reference)
#include <cuda_runtime.h>

typedef unsigned long long u64;

#define D      32
#define KNN    4
#define NF     2048
#define NSMP   16384
#define SPB    128       // samples per phase-A block
#define TILE   32
#define AWARPS 12        // 2 groups x 6 warps
#define SPLIT  8         // max apply blocks per center

// ---------------- packed f32x2 helpers (sm_103a FFMA2 path) ----------------
__device__ __forceinline__ u64 fma2(u64 a, u64 b, u64 c) {
    u64 r;
    asm("fma.rn.f32x2 %0, %1, %2, %3;" : "=l"(r) : "l"(a), "l"(b), "l"(c));
    return r;
}
__device__ __forceinline__ u64 add2(u64 a, u64 b) {
    u64 r;
    asm("add.rn.f32x2 %0, %1, %2;" : "=l"(r) : "l"(a), "l"(b));
    return r;
}
__device__ __forceinline__ void unpack2(u64 a, float& lo, float& hi) {
    asm("mov.b64 {%0, %1}, %2;" : "=f"(lo), "=f"(hi) : "l"(a));
}
__device__ __forceinline__ u64 pack2(float a, float b) {
    u64 r;
    asm("mov.b64 %0, {%1, %2};" : "=l"(r) : "f"(a), "f"(b));
    return r;
}

// ---------------- device scratch (exact CSR, cannot overflow) ----------------
__device__ float g_cnorm[NF];
__device__ int   g_cnt[NF];
__device__ int   g_off[NF];
__device__ int   g_fill[NF];
__device__ int   g_sel[NSMP * KNN];
__device__ int   g_bins[NSMP * KNN];

// ---------------- zero outputs + counters ----------------
__global__ void zero_kernel(float* __restrict__ y, int n_out, int n_fcns) {
    int i = blockIdx.x * blockDim.x + threadIdx.x;
    if (i < n_out) y[i] = 0.0f;
    if (i < n_fcns) { g_cnt[i] = 0; g_fill[i] = 0; }
}

// ---------------- per-center squared norms ----------------
__global__ void cnorm_kernel(const float* __restrict__ ctrs, int n_fcns) {
    int f = blockIdx.x * blockDim.x + threadIdx.x;
    if (f < n_fcns) {
        const float4* c4 = (const float4*)(ctrs + (size_t)f * D);
        float s = 0.0f;
#pragma unroll
        for (int j = 0; j < D / 4; j++) {
            float4 q = __ldg(c4 + j);
            s += q.x * q.x + q.y * q.y + q.z * q.z + q.w * q.w;
        }
        g_cnorm[f] = s;
    }
}

// select-only stable top-4 insert; SAFE when sc >= d3 (no-op). Strict <.
#define INS4(sc, f, d0, d1, d2, d3, i0, i1, i2, i3) do {                        \
    bool h0 = (sc) < d0, h1 = (sc) < d1, h2 = (sc) < d2, h3 = (sc) < d3;        \
    float n3 = h3 ? (h2 ? d2 : (sc)) : d3;  int m3 = h3 ? (h2 ? i2 : (f)) : i3; \
    float n2 = h2 ? (h1 ? d1 : (sc)) : d2;  int m2 = h2 ? (h1 ? i1 : (f)) : i2; \
    float n1 = h1 ? (h0 ? d0 : (sc)) : d1;  int m1 = h1 ? (h0 ? i0 : (f)) : i1; \
    d0 = h0 ? (sc) : d0;                    i0 = h0 ? (f) : i0;                 \
    d1 = n1; i1 = m1; d2 = n2; i2 = m2; d3 = n3; i3 = m3;                       \
} while (0)

// ---------------- phase A: top-4 selection, per-sample winners + counts ----
// Block = 384 threads = 12 warps = 2 groups of 6, 128 samples.
// Group g's 6 warps serve samples [64g, 64g+64); lane owns (lane, lane+32).
// Warp-in-group wg scans a tile-granular shard of all centers. 24 candidates
// per sample merged lexicographically -> g_sel + g_cnt.
__global__ __launch_bounds__(384, 1) void pwlA_kernel(
    const float* __restrict__ x,
    const float* __restrict__ ctrs,
    int n_fcns)
{
    extern __shared__ __align__(16) char smem[];
    float* s_ctr = (float*)smem;                         // [12][32*32]
    float* s_cn  = s_ctr + AWARPS * TILE * D;            // [12][32]
    float* s_cd  = s_cn + AWARPS * TILE;                 // [128][24]
    int*   s_ci  = (int*)(s_cd + SPB * 24);              // [128][24]

    const int lane = threadIdx.x & 31;
    const int w    = threadIdx.x >> 5;
    const int g    = w / 6;
    const int wg   = w % 6;
    const int rowA = blockIdx.x * SPB + g * 64 + lane;
    const int rowB = rowA + 32;

    // ---- load both sample rows as packed (-2*x) ----
    u64 xpA[16], xpB[16];
    {
        const float4* ga = (const float4*)(x + (size_t)rowA * D);
        const float4* gb = (const float4*)(x + (size_t)rowB * D);
#pragma unroll
        for (int j = 0; j < 8; j++) {
            float4 qa = __ldg(ga + j);
            float4 qb = __ldg(gb + j);
            xpA[2 * j]     = pack2(-2.0f * qa.x, -2.0f * qa.y);
            xpA[2 * j + 1] = pack2(-2.0f * qa.z, -2.0f * qa.w);
            xpB[2 * j]     = pack2(-2.0f * qb.x, -2.0f * qb.y);
            xpB[2 * j + 1] = pack2(-2.0f * qb.z, -2.0f * qb.w);
        }
    }

    // ---- tile-granular shard for this warp within its group ----
    const int NTT  = n_fcns / TILE;            // 64
    const int base = NTT / 6, rem = NTT % 6;
    const int tb   = wg * base + min(wg, rem);
    const int te   = tb + base + (wg < rem ? 1 : 0);

    float* my_ctr = s_ctr + w * TILE * D;
    float* my_cn  = s_cn + w * TILE;

    float A0 = 3.4e38f, A1 = 3.4e38f, A2 = 3.4e38f, A3 = 3.4e38f;
    float B0 = 3.4e38f, B1 = 3.4e38f, B2 = 3.4e38f, B3 = 3.4e38f;
    int   Ai0 = 0, Ai1 = 0, Ai2 = 0, Ai3 = 0;
    int   Bi0 = 0, Bi1 = 0, Bi2 = 0, Bi3 = 0;

    const float4* cg4 = (const float4*)ctrs;

    for (int tt = tb; tt < te; tt++) {
        const int t = tt * TILE;
        __syncwarp();
        // stage 32 centers for this warp (exact tiles, no guards)
#pragma unroll
        for (int i = 0; i < 8; i++) {
            int e = i * 32 + lane;                             // 0..255
            ((float4*)my_ctr)[e] = __ldg(cg4 + (size_t)(t + (e >> 3)) * 8 + (e & 7));
        }
        my_cn[lane] = g_cnorm[t + lane];
        __syncwarp();

#pragma unroll 2
        for (int ff = 0; ff < TILE; ff++) {
            const ulonglong2* c2 = (const ulonglong2*)(my_ctr + ff * D);
            u64 cnp = (u64)__float_as_uint(my_cn[ff]);         // (cnorm, 0)
            u64 a0 = 0ull, a1 = 0ull, a2 = 0ull, a3 = cnp;
            u64 b0 = 0ull, b1 = 0ull, b2 = 0ull, b3 = cnp;
#pragma unroll
            for (int j = 0; j < 4; j++) {
                ulonglong2 qa = c2[2 * j];
                ulonglong2 qb = c2[2 * j + 1];
                a0 = fma2(xpA[4 * j + 0], qa.x, a0);
                b0 = fma2(xpB[4 * j + 0], qa.x, b0);
                a1 = fma2(xpA[4 * j + 1], qa.y, a1);
                b1 = fma2(xpB[4 * j + 1], qa.y, b1);
                a2 = fma2(xpA[4 * j + 2], qb.x, a2);
                b2 = fma2(xpB[4 * j + 2], qb.x, b2);
                a3 = fma2(xpA[4 * j + 3], qb.y, a3);
                b3 = fma2(xpB[4 * j + 3], qb.y, b3);
            }
            u64 ra = add2(add2(a0, a1), add2(a2, a3));
            u64 rb = add2(add2(b0, b1), add2(b2, b3));
            float la, ha, lb, hb;
            unpack2(ra, la, ha);
            unpack2(rb, lb, hb);
            float scA = la + ha;               // == cnorm - 2*dot (rank-equiv)
            float scB = lb + hb;
            const int f = t + ff;
            if (scA < A3 || scB < B3) {        // rare after warmup
                INS4(scA, f, A0, A1, A2, A3, Ai0, Ai1, Ai2, Ai3);
                INS4(scB, f, B0, B1, B2, B3, Bi0, Bi1, Bi2, Bi3);
            }
        }
    }

    // ---- publish candidates (24 per sample) ----
    {
        const int ra = g * 64 + lane;
        float* cd = s_cd + ra * 24 + wg * KNN;
        int*   ci = s_ci + ra * 24 + wg * KNN;
        cd[0] = A0; cd[1] = A1; cd[2] = A2; cd[3] = A3;
        ci[0] = Ai0; ci[1] = Ai1; ci[2] = Ai2; ci[3] = Ai3;
        cd = s_cd + (ra + 32) * 24 + wg * KNN;
        ci = s_ci + (ra + 32) * 24 + wg * KNN;
        cd[0] = B0; cd[1] = B1; cd[2] = B2; cd[3] = B3;
        ci[0] = Bi0; ci[1] = Bi1; ci[2] = Bi2; ci[3] = Bi3;
    }
    __syncthreads();

    // ---- merge 24 -> 4 per sample; record winners + counts ----
    if (threadIdx.x < SPB) {
        const int ms = threadIdx.x;
        const int n  = blockIdx.x * SPB + ms;
        float cd[24];
        int   ci[24];
#pragma unroll
        for (int j = 0; j < 24; j++) {
            cd[j] = s_cd[ms * 24 + j];
            ci[j] = s_ci[ms * 24 + j];
        }
#pragma unroll
        for (int k = 0; k < KNN; k++) {
            int best = 0;
#pragma unroll
            for (int j = 1; j < 24; j++) {
                // lexicographic (dist, idx): matches top_k tie-break
                if (cd[j] < cd[best] || (cd[j] == cd[best] && ci[j] < ci[best]))
                    best = j;
            }
            int f = ci[best];
            cd[best] = 3.4e38f;
            g_sel[n * KNN + k] = f;
            atomicAdd(&g_cnt[f], 1);
        }
    }
}

// ---------------- exclusive prefix sum of g_cnt (one block, 256 threads) ----
__global__ void scan_kernel(int n_fcns) {
    __shared__ int part[256];
    const int t = threadIdx.x;          // handles entries [8t, 8t+8)
    int v[8];
    int s = 0;
#pragma unroll
    for (int j = 0; j < 8; j++) {
        int tmp = g_cnt[t * 8 + j];
        v[j] = s;
        s += tmp;
    }
    part[t] = s;
    __syncthreads();
    // Hillis-Steele inclusive scan on part[256]
    for (int off = 1; off < 256; off <<= 1) {
        int val = (t >= off) ? part[t - off] : 0;
        __syncthreads();
        part[t] += val;
        __syncthreads();
    }
    int base = (t == 0) ? 0 : part[t - 1];
#pragma unroll
    for (int j = 0; j < 8; j++)
        g_off[t * 8 + j] = base + v[j];
}

// ---------------- fill CSR bins ----------------
__global__ void fill_kernel(int total) {
    int i = blockIdx.x * blockDim.x + threadIdx.x;
    if (i < total) {
        int f = g_sel[i];
        int pos = atomicAdd(&g_fill[f], 1);
        g_bins[g_off[f] + pos] = i >> 2;    // sample id
    }
}

// ---------------- phase B: center-major apply ----------------
// Blocks (f, s): W_f/c_f/off_f staged once per surviving block; large bins
// split across up to SPLIT blocks (chunk >= 64; extras exit before W load).
__global__ __launch_bounds__(256) void apply_kernel(
    const float* __restrict__ x,
    const float* __restrict__ ctrs,
    const float* __restrict__ wts,
    const float* __restrict__ offs,
    float* __restrict__ y)
{
    const int f   = blockIdx.x;
    const int cnt = g_cnt[f];
    if (cnt == 0) return;
    const int chunk = max(64, (cnt + SPLIT - 1) / SPLIT);
    const int start = blockIdx.y * chunk;
    if (start >= cnt) return;
    const int end = min(cnt, start + chunk);
    const int b0  = g_off[f];

    __shared__ float sW[D * D];
    __shared__ float sc[D];
    __shared__ float so[D];

    const int tid  = threadIdx.x;
    const int lane = tid & 31;
    const int w    = tid >> 5;

    ((float4*)sW)[tid] = __ldg((const float4*)(wts + (size_t)f * D * D) + tid);
    if (tid < D) {
        sc[tid] = __ldg(ctrs + (size_t)f * D + tid);
        so[tid] = __ldg(offs + (size_t)f * D + tid);
    }
    __syncthreads();

    // per-warp contiguous sub-range, 2 samples in flight
    const int len = end - start;
    const int per = (len + 7) / 8;
    int i  = start + w * per;
    int we = min(end, i + per);

    for (; i + 1 < we; i += 2) {
        const int n0 = g_bins[b0 + i];
        const int n1 = g_bins[b0 + i + 1];
        const float4* x0 = (const float4*)(x + (size_t)n0 * D);
        const float4* x1 = (const float4*)(x + (size_t)n1 * D);
        float a0 = so[lane], a1 = 0.0f;
        float c0 = so[lane], c1 = 0.0f;
#pragma unroll
        for (int j = 0; j < 8; j++) {
            float4 q0 = __ldg(x0 + j);
            float4 q1 = __ldg(x1 + j);
            a0 = fmaf(q0.x - sc[4 * j + 0], sW[(4 * j + 0) * D + lane], a0);
            c0 = fmaf(q1.x - sc[4 * j + 0], sW[(4 * j + 0) * D + lane], c0);
            a1 = fmaf(q0.y - sc[4 * j + 1], sW[(4 * j + 1) * D + lane], a1);
            c1 = fmaf(q1.y - sc[4 * j + 1], sW[(4 * j + 1) * D + lane], c1);
            a0 = fmaf(q0.z - sc[4 * j + 2], sW[(4 * j + 2) * D + lane], a0);
            c0 = fmaf(q1.z - sc[4 * j + 2], sW[(4 * j + 2) * D + lane], c0);
            a1 = fmaf(q0.w - sc[4 * j + 3], sW[(4 * j + 3) * D + lane], a1);
            c1 = fmaf(q1.w - sc[4 * j + 3], sW[(4 * j + 3) * D + lane], c1);
        }
        atomicAdd(y + (size_t)n0 * D + lane, a0 + a1);
        atomicAdd(y + (size_t)n1 * D + lane, c0 + c1);
    }
    if (i < we) {
        const int n0 = g_bins[b0 + i];
        const float4* x0 = (const float4*)(x + (size_t)n0 * D);
        float a0 = so[lane], a1 = 0.0f;
#pragma unroll
        for (int j = 0; j < 8; j++) {
            float4 q0 = __ldg(x0 + j);
            a0 = fmaf(q0.x - sc[4 * j + 0], sW[(4 * j + 0) * D + lane], a0);
            a1 = fmaf(q0.y - sc[4 * j + 1], sW[(4 * j + 1) * D + lane], a1);
            a0 = fmaf(q0.z - sc[4 * j + 2], sW[(4 * j + 2) * D + lane], a0);
            a1 = fmaf(q0.w - sc[4 * j + 3], sW[(4 * j + 3) * D + lane], a1);
        }
        atomicAdd(y + (size_t)n0 * D + lane, a0 + a1);
    }
}

// ---------------- launch ----------------
#define DYN_A (AWARPS * TILE * D * 4 + AWARPS * TILE * 4 + SPB * 24 * 8)

extern "C" void kernel_launch(void* const* d_in, const int* in_sizes, int n_in,
                              void* d_out, int out_size)
{
    const float* x    = (const float*)d_in[0];
    const float* ctrs = (const float*)d_in[1];
    const float* wts  = (const float*)d_in[2];
    const float* offs = (const float*)d_in[3];
    float* y = (float*)d_out;

    int n_smps = in_sizes[0] / D;
    int n_fcns = in_sizes[1] / D;

    cudaFuncSetAttribute(pwlA_kernel,
                         cudaFuncAttributeMaxDynamicSharedMemorySize, DYN_A);

    zero_kernel<<<(out_size + 255) / 256, 256>>>(y, out_size, n_fcns);
    cnorm_kernel<<<(n_fcns + 255) / 256, 256>>>(ctrs, n_fcns);
    pwlA_kernel<<<n_smps / SPB, 384, DYN_A>>>(x, ctrs, n_fcns);
    scan_kernel<<<1, 256>>>(n_fcns);
    fill_kernel<<<(n_smps * KNN + 255) / 256, 256>>>(n_smps * KNN);
    dim3 agrid(n_fcns, SPLIT);
    apply_kernel<<<agrid, 256>>>(x, ctrs, wts, offs, y);
}